// round 3
// baseline (speedup 1.0000x reference)
#include <cuda_runtime.h>

// Problem constants
#define W_DIM 512
#define H_DIM 512
#define B_DIM 8
#define C_DIM 32
#define NBLK  128           // 8 batches * 16 row-tiles of 32 rows
#define NTHR  256

// Scratch: transposed input/output in (W, B, H, C) layout, C contiguous.
__device__ float    g_Xt[W_DIM * B_DIM * H_DIM * C_DIM];   // 256 MB
__device__ float    g_Yt[W_DIM * B_DIM * H_DIM * C_DIM];   // 256 MB
__device__ unsigned g_lo[NBLK];   // "row 0 of column w published" counters
__device__ unsigned g_hi[NBLK];   // "row 31 of column w published" counters

// ---- fast math -------------------------------------------------------------
__device__ __forceinline__ float tanh_fast(float x) {
    float y; asm("tanh.approx.f32 %0, %1;" : "=f"(y) : "f"(x)); return y;
}
__device__ __forceinline__ float sigmoid_fast(float x) {
    return fmaf(0.5f, tanh_fast(0.5f * x), 0.5f);
}

// ---- acquire/release flag ops ---------------------------------------------
__device__ __forceinline__ unsigned ld_acq(const unsigned* p) {
    unsigned v; asm volatile("ld.acquire.gpu.global.u32 %0, [%1];" : "=r"(v) : "l"(p)); return v;
}
__device__ __forceinline__ void st_rel(unsigned* p, unsigned v) {
    asm volatile("st.release.gpu.global.u32 [%0], %1;" :: "l"(p), "r"(v));
}

// ---------------------------------------------------------------------------
// Transpose (B,C,H,W) -> (W,B,H,C)
// ---------------------------------------------------------------------------
__global__ __launch_bounds__(256) void transpose_in_kernel(const float* __restrict__ states) {
    __shared__ float tile[32][33];
    const int wt = blockIdx.x, h = blockIdx.y, b = blockIdx.z;
    const int w0 = wt * 32;
    const int t  = threadIdx.x;
    const int lo = t & 31, g = t >> 5;
#pragma unroll
    for (int i = 0; i < 4; ++i) {
        int cc = g * 4 + i;
        tile[cc][lo] = states[((size_t)(b * 32 + cc) * 512 + h) * 512 + (w0 + lo)];
    }
    __syncthreads();
#pragma unroll
    for (int i = 0; i < 4; ++i) {
        int ww = g * 4 + i;
        g_Xt[((size_t)((w0 + ww) * 8 + b) * 512 + h) * 32 + lo] = tile[lo][ww];
    }
}

// ---------------------------------------------------------------------------
// Transpose (W,B,H,C) -> (B,C,H,W)
// ---------------------------------------------------------------------------
__global__ __launch_bounds__(256) void transpose_out_kernel(float* __restrict__ out) {
    __shared__ float tile[32][33];
    const int wt = blockIdx.x, h = blockIdx.y, b = blockIdx.z;
    const int w0 = wt * 32;
    const int t  = threadIdx.x;
    const int lo = t & 31, g = t >> 5;
#pragma unroll
    for (int i = 0; i < 4; ++i) {
        int ww = g * 4 + i;
        tile[ww][lo] = g_Yt[((size_t)((w0 + ww) * 8 + b) * 512 + h) * 32 + lo];
    }
    __syncthreads();
#pragma unroll
    for (int i = 0; i < 4; ++i) {
        int cc = g * 4 + i;
        out[((size_t)(b * 32 + cc) * 512 + h) * 512 + (w0 + lo)] = tile[lo][cc];
    }
}

// ---------------------------------------------------------------------------
// Persistent scan kernel. 128 blocks, each owns 32 (b,h) rows for all 511
// steps. ONE __syncthreads per step; neighbor handoff via split per-edge
// release/acquire flags (warp 0 publishes row 0 -> lo flag, warp 7 publishes
// row 31 -> hi flag, immediately after their own stores + __syncwarp).
//
// smem layout (floats):
//   sWih  : 96 x 100 (stride % 32 == 4 -> conflict-free float4) = 9600
//   sWhh  : 96 x 36                                             = 3456
//   buf0  : 34 x 32  (prev column + 2 halo rows)                = 1088
//   buf1  : 34 x 32                                             = 1088
//   sCur0 : 32 x 32  (current input column)                     = 1024
//   sCur1 : 32 x 32                                             = 1024
// total 17280 floats = 69120 bytes (dynamic)
// ---------------------------------------------------------------------------
#define SM_WIH  0
#define SM_WHH  (SM_WIH + 96 * 100)
#define SM_BUF0 (SM_WHH + 96 * 36)
#define SM_BUF1 (SM_BUF0 + 34 * 32)
#define SM_CUR0 (SM_BUF1 + 34 * 32)
#define SM_CUR1 (SM_CUR0 + 32 * 32)
#define SM_FLOATS (SM_CUR1 + 32 * 32)

__global__ __launch_bounds__(NTHR, 1) void scan_kernel(
    const float* __restrict__ Wih, const float* __restrict__ bih,
    const float* __restrict__ Whh, const float* __restrict__ bhh)
{
    extern __shared__ float sm[];
    float* sWih = sm + SM_WIH;
    float* sWhh = sm + SM_WHH;
    float* bufA[2] = { sm + SM_BUF0, sm + SM_BUF1 };
    float* curA[2] = { sm + SM_CUR0, sm + SM_CUR1 };
    __shared__ unsigned sBase;

    const int tid  = threadIdx.x;
    const int beta = blockIdx.x;
    const int b    = beta >> 4;
    const int tile = beta & 15;
    const int h0   = tile * 32;
    const int c    = tid & 31;        // channel
    const int rq   = tid >> 5;        // warp id = row quad: rows rq*4 .. rq*4+3

    if (tid == 0) sBase = ld_acq(&g_lo[beta]);   // lo==hi at every run boundary

    for (int i = tid; i < 96 * 96; i += NTHR) sWih[(i / 96) * 100 + (i % 96)] = Wih[i];
    for (int i = tid; i < 96 * 32; i += NTHR) sWhh[(i / 32) * 36  + (i % 32)] = Whh[i];

    const float br0 = bih[c]      + bhh[c];
    const float bz0 = bih[32 + c] + bhh[32 + c];
    const float bni = bih[64 + c];
    const float bnh = bhh[64 + c];

    // zero halo slots of both buffers (edge tiles never overwrite them)
    if (tid < 32) { bufA[0][tid] = 0.0f; bufA[1][tid] = 0.0f; }
    else if (tid < 64) { bufA[0][33 * 32 + (tid - 32)] = 0.0f; bufA[1][33 * 32 + (tid - 32)] = 0.0f; }
    __syncthreads();

    // Publish column 0 = input column 0 (identity passthrough) into buf0
    for (int i = tid; i < 1024; i += NTHR) {
        int r = i >> 5, cc = i & 31;
        size_t gi = ((size_t)b * 512 + (h0 + r)) * 32 + cc;   // w = 0
        float v = g_Xt[gi];
        bufA[0][(1 + r) * 32 + cc] = v;
        __stcg(&g_Yt[gi], v);
    }
    __syncthreads();
    if (tid == 0) { st_rel(&g_lo[beta], sBase + 1); st_rel(&g_hi[beta], sBase + 1); }

    for (int w = 1; w < W_DIM; ++w) {
        float* bufPrev = bufA[(w - 1) & 1];   // holds column w-1 (+ halos)
        float* bufCur  = bufA[w & 1];         // receives column w
        float* sCur    = curA[w & 1];         // current input column

        // Current input column, coalesced float4 (256 threads x 16B = 4 KB)
        {
            const float4* src = (const float4*)&g_Xt[((size_t)(w * 8 + b) * 512 + h0) * 32];
            ((float4*)sCur)[tid] = src[tid];
        }

        // Warp 0: fetch lower halo (tile-1's row 31 -> hi flag).
        // Warp 1: fetch upper halo (tile+1's row 0 -> lo flag).
        if (tid < 64) {
            const bool down = tid < 32;
            const int  lane = tid & 31;
            const bool valid = down ? (tile > 0) : (tile < 15);
            if (valid) {
                const int nb = down ? beta - 1 : beta + 1;
                if (lane == 0) {
                    const unsigned tgt = sBase + (unsigned)w;
                    if (down) { while (ld_acq(&g_hi[nb]) < tgt) { } }
                    else      { while (ld_acq(&g_lo[nb]) < tgt) { } }
                }
                __syncwarp();
                const int hh = down ? (h0 - 1) : (h0 + 32);
                float v = __ldcg(&g_Yt[((size_t)((w - 1) * 8 + b) * 512 + hh) * 32 + lane]);
                bufPrev[(down ? 0 : 33) * 32 + lane] = v;
            }
        }
        __syncthreads();   // the ONLY per-step barrier

        // ---- compute: 4 rows x 1 channel per thread -----------------------
        float ar[4], az[4], ani[4], anh[4];
#pragma unroll
        for (int i = 0; i < 4; ++i) { ar[i] = br0; az[i] = bz0; ani[i] = bni; anh[i] = bnh; }

        // i-part: x(96 = prev rows h-1,h,h+1 contiguous in bufPrev) @ Wih^T
#pragma unroll 8
        for (int kq = 0; kq < 24; ++kq) {
            float4 wr = *(const float4*)&sWih[(c)      * 100 + kq * 4];
            float4 wz = *(const float4*)&sWih[(32 + c) * 100 + kq * 4];
            float4 wn = *(const float4*)&sWih[(64 + c) * 100 + kq * 4];
#pragma unroll
            for (int i = 0; i < 4; ++i) {
                float4 xv = *(const float4*)&bufPrev[(rq * 4 + i) * 32 + kq * 4];
                ar[i]  = fmaf(xv.x, wr.x, fmaf(xv.y, wr.y, fmaf(xv.z, wr.z, fmaf(xv.w, wr.w, ar[i]))));
                az[i]  = fmaf(xv.x, wz.x, fmaf(xv.y, wz.y, fmaf(xv.z, wz.z, fmaf(xv.w, wz.w, az[i]))));
                ani[i] = fmaf(xv.x, wn.x, fmaf(xv.y, wn.y, fmaf(xv.z, wn.z, fmaf(xv.w, wn.w, ani[i]))));
            }
        }
        // h-part: cur col (32) @ Whh^T
#pragma unroll
        for (int kq = 0; kq < 8; ++kq) {
            float4 wr = *(const float4*)&sWhh[(c)      * 36 + kq * 4];
            float4 wz = *(const float4*)&sWhh[(32 + c) * 36 + kq * 4];
            float4 wn = *(const float4*)&sWhh[(64 + c) * 36 + kq * 4];
#pragma unroll
            for (int i = 0; i < 4; ++i) {
                float4 hv = *(const float4*)&sCur[(rq * 4 + i) * 32 + kq * 4];
                ar[i]  = fmaf(hv.x, wr.x, fmaf(hv.y, wr.y, fmaf(hv.z, wr.z, fmaf(hv.w, wr.w, ar[i]))));
                az[i]  = fmaf(hv.x, wz.x, fmaf(hv.y, wz.y, fmaf(hv.z, wz.z, fmaf(hv.w, wz.w, az[i]))));
                anh[i] = fmaf(hv.x, wn.x, fmaf(hv.y, wn.y, fmaf(hv.z, wn.z, fmaf(hv.w, wn.w, anh[i]))));
            }
        }

        float outv[4];
#pragma unroll
        for (int i = 0; i < 4; ++i) {
            float rg = sigmoid_fast(ar[i]);
            float zg = sigmoid_fast(az[i]);
            float ng = tanh_fast(fmaf(rg, anh[i], ani[i]));
            float cv = sCur[(rq * 4 + i) * 32 + c];
            outv[i]  = fmaf(ng - cv, zg, cv);   // n*z + cur*(1-z)
        }

        // write own rows into the other buffer + global (double-buffered: no
        // barrier needed here — next step's barrier orders all consumers)
#pragma unroll
        for (int i = 0; i < 4; ++i) {
            int r = rq * 4 + i;
            bufCur[(1 + r) * 32 + c] = outv[i];
            __stcg(&g_Yt[((size_t)(w * 8 + b) * 512 + (h0 + r)) * 32 + c], outv[i]);
        }
        // Edge warps publish their rows immediately (warp-scoped release):
        if (rq == 0) {                    // warp 0 stored row 0
            __syncwarp();
            if (c == 0) st_rel(&g_lo[beta], sBase + (unsigned)(w + 1));
        } else if (rq == 7) {             // warp 7 stored row 31
            __syncwarp();
            if (c == 0) st_rel(&g_hi[beta], sBase + (unsigned)(w + 1));
        }
    }
}

// ---------------------------------------------------------------------------
extern "C" void kernel_launch(void* const* d_in, const int* in_sizes, int n_in,
                              void* d_out, int out_size) {
    const float* states = (const float*)d_in[0];
    const float* wih    = (const float*)d_in[1];
    const float* bih    = (const float*)d_in[2];
    const float* whh    = (const float*)d_in[3];
    const float* bhh    = (const float*)d_in[4];
    float* out = (float*)d_out;

    cudaFuncSetAttribute(scan_kernel, cudaFuncAttributeMaxDynamicSharedMemorySize,
                         SM_FLOATS * (int)sizeof(float));

    dim3 tgrid(W_DIM / 32, H_DIM, B_DIM);
    transpose_in_kernel<<<tgrid, 256>>>(states);
    scan_kernel<<<NBLK, NTHR, SM_FLOATS * sizeof(float)>>>(wih, bih, whh, bhh);
    transpose_out_kernel<<<tgrid, 256>>>(out);
}

// round 4
// speedup vs baseline: 1.0820x; 1.0820x over previous
#include <cuda_runtime.h>

// Problem constants
#define W_DIM 512
#define H_DIM 512
#define B_DIM 8
#define C_DIM 32
#define NBLK  128           // 8 batches * 16 row-tiles of 32 rows
#define NTHR  256

// Scratch: transposed input/output in (W, B, H, C) layout, C contiguous.
__device__ float    g_Xt[W_DIM * B_DIM * H_DIM * C_DIM];   // 256 MB
__device__ float    g_Yt[W_DIM * B_DIM * H_DIM * C_DIM];   // 256 MB
__device__ unsigned g_lo[NBLK];   // "row 0 of column w published" counters
__device__ unsigned g_hi[NBLK];   // "row 31 of column w published" counters

// ---- fast math -------------------------------------------------------------
__device__ __forceinline__ float tanh_fast(float x) {
    float y; asm("tanh.approx.f32 %0, %1;" : "=f"(y) : "f"(x)); return y;
}
__device__ __forceinline__ float sigmoid_fast(float x) {
    return fmaf(0.5f, tanh_fast(0.5f * x), 0.5f);
}

// ---- flag ops --------------------------------------------------------------
// Relaxed strong-GPU load: L2 read, NO acquire fence, NO L1 invalidation.
__device__ __forceinline__ unsigned ld_rlx(const unsigned* p) {
    unsigned v;
    asm volatile("ld.relaxed.gpu.global.u32 %0, [%1];" : "=r"(v) : "l"(p) : "memory");
    return v;
}
// Release store: orders all prior stores (data) before the flag in L2. Cheap.
__device__ __forceinline__ void st_rel(unsigned* p, unsigned v) {
    asm volatile("st.release.gpu.global.u32 [%0], %1;" :: "l"(p), "r"(v) : "memory");
}

// ---------------------------------------------------------------------------
// Transpose (B,C,H,W) -> (W,B,H,C)
// ---------------------------------------------------------------------------
__global__ __launch_bounds__(256) void transpose_in_kernel(const float* __restrict__ states) {
    __shared__ float tile[32][33];
    const int wt = blockIdx.x, h = blockIdx.y, b = blockIdx.z;
    const int w0 = wt * 32;
    const int t  = threadIdx.x;
    const int lo = t & 31, g = t >> 5;
#pragma unroll
    for (int i = 0; i < 4; ++i) {
        int cc = g * 4 + i;
        tile[cc][lo] = states[((size_t)(b * 32 + cc) * 512 + h) * 512 + (w0 + lo)];
    }
    __syncthreads();
#pragma unroll
    for (int i = 0; i < 4; ++i) {
        int ww = g * 4 + i;
        g_Xt[((size_t)((w0 + ww) * 8 + b) * 512 + h) * 32 + lo] = tile[lo][ww];
    }
}

// ---------------------------------------------------------------------------
// Transpose (W,B,H,C) -> (B,C,H,W)
// ---------------------------------------------------------------------------
__global__ __launch_bounds__(256) void transpose_out_kernel(float* __restrict__ out) {
    __shared__ float tile[32][33];
    const int wt = blockIdx.x, h = blockIdx.y, b = blockIdx.z;
    const int w0 = wt * 32;
    const int t  = threadIdx.x;
    const int lo = t & 31, g = t >> 5;
#pragma unroll
    for (int i = 0; i < 4; ++i) {
        int ww = g * 4 + i;
        tile[ww][lo] = g_Yt[((size_t)((w0 + ww) * 8 + b) * 512 + h) * 32 + lo];
    }
    __syncthreads();
#pragma unroll
    for (int i = 0; i < 4; ++i) {
        int cc = g * 4 + i;
        out[((size_t)(b * 32 + cc) * 512 + h) * 512 + (w0 + lo)] = tile[lo][cc];
    }
}

// ---------------------------------------------------------------------------
// Persistent scan kernel. 128 blocks, each owns 32 (b,h) rows for all 511
// steps. ONE __syncthreads per step; neighbor handoff via split per-edge
// flags: producer edge warps store rows then st.release the flag; consumers
// spin with RELAXED L2 loads (no acquire -> no L1-invalidate storm) and read
// halo data with __ldcg (L2), which release ordering makes safe.
//
// smem layout (floats):
//   sWih  : 96 x 100 (stride % 32 == 4 -> conflict-free float4) = 9600
//   sWhh  : 96 x 36                                             = 3456
//   buf0  : 34 x 32  (prev column + 2 halo rows)                = 1088
//   buf1  : 34 x 32                                             = 1088
//   sCur0 : 32 x 32  (current input column)                     = 1024
//   sCur1 : 32 x 32                                             = 1024
// total 17280 floats = 69120 bytes (dynamic)
// ---------------------------------------------------------------------------
#define SM_WIH  0
#define SM_WHH  (SM_WIH + 96 * 100)
#define SM_BUF0 (SM_WHH + 96 * 36)
#define SM_BUF1 (SM_BUF0 + 34 * 32)
#define SM_CUR0 (SM_BUF1 + 34 * 32)
#define SM_CUR1 (SM_CUR0 + 32 * 32)
#define SM_FLOATS (SM_CUR1 + 32 * 32)

__global__ __launch_bounds__(NTHR, 1) void scan_kernel(
    const float* __restrict__ Wih, const float* __restrict__ bih,
    const float* __restrict__ Whh, const float* __restrict__ bhh)
{
    extern __shared__ float sm[];
    float* sWih = sm + SM_WIH;
    float* sWhh = sm + SM_WHH;
    float* bufA[2] = { sm + SM_BUF0, sm + SM_BUF1 };
    float* curA[2] = { sm + SM_CUR0, sm + SM_CUR1 };
    __shared__ unsigned sBase;

    const int tid  = threadIdx.x;
    const int beta = blockIdx.x;
    const int b    = beta >> 4;
    const int tile = beta & 15;
    const int h0   = tile * 32;
    const int c    = tid & 31;        // channel
    const int rq   = tid >> 5;        // warp id = row quad: rows rq*4 .. rq*4+3

    if (tid == 0) sBase = ld_rlx(&g_lo[beta]);   // lo==hi at every run boundary

    for (int i = tid; i < 96 * 96; i += NTHR) sWih[(i / 96) * 100 + (i % 96)] = Wih[i];
    for (int i = tid; i < 96 * 32; i += NTHR) sWhh[(i / 32) * 36  + (i % 32)] = Whh[i];

    const float br0 = bih[c]      + bhh[c];
    const float bz0 = bih[32 + c] + bhh[32 + c];
    const float bni = bih[64 + c];
    const float bnh = bhh[64 + c];

    // zero halo slots of both buffers (edge tiles never overwrite them)
    if (tid < 32) { bufA[0][tid] = 0.0f; bufA[1][tid] = 0.0f; }
    else if (tid < 64) { bufA[0][33 * 32 + (tid - 32)] = 0.0f; bufA[1][33 * 32 + (tid - 32)] = 0.0f; }
    __syncthreads();

    // Publish column 0 = input column 0 (identity passthrough) into buf0
    for (int i = tid; i < 1024; i += NTHR) {
        int r = i >> 5, cc = i & 31;
        size_t gi = ((size_t)b * 512 + (h0 + r)) * 32 + cc;   // w = 0
        float v = g_Xt[gi];
        bufA[0][(1 + r) * 32 + cc] = v;
        __stcg(&g_Yt[gi], v);
    }
    __syncthreads();
    if (tid == 0) { st_rel(&g_lo[beta], sBase + 1); st_rel(&g_hi[beta], sBase + 1); }

    for (int w = 1; w < W_DIM; ++w) {
        float* bufPrev = bufA[(w - 1) & 1];   // holds column w-1 (+ halos)
        float* bufCur  = bufA[w & 1];         // receives column w
        float* sCur    = curA[w & 1];         // current input column

        // Current input column, coalesced float4 (256 threads x 16B = 4 KB)
        {
            const float4* src = (const float4*)&g_Xt[((size_t)(w * 8 + b) * 512 + h0) * 32];
            ((float4*)sCur)[tid] = src[tid];
        }

        // Warp 0: fetch lower halo (tile-1's row 31 -> hi flag).
        // Warp 1: fetch upper halo (tile+1's row 0 -> lo flag).
        if (tid < 64) {
            const bool down = tid < 32;
            const int  lane = tid & 31;
            const bool valid = down ? (tile > 0) : (tile < 15);
            if (valid) {
                const int nb = down ? beta - 1 : beta + 1;
                if (lane == 0) {
                    const unsigned tgt = sBase + (unsigned)w;
                    const unsigned* fp = down ? &g_hi[nb] : &g_lo[nb];
                    while (ld_rlx(fp) < tgt) { }   // relaxed L2 poll, no IVALL
                }
                __syncwarp();
                const int hh = down ? (h0 - 1) : (h0 + 32);
                float v = __ldcg(&g_Yt[((size_t)((w - 1) * 8 + b) * 512 + hh) * 32 + lane]);
                bufPrev[(down ? 0 : 33) * 32 + lane] = v;
            }
        }
        __syncthreads();   // the ONLY per-step barrier

        // ---- compute: 4 rows x 1 channel per thread -----------------------
        float ar[4], az[4], ani[4], anh[4];
#pragma unroll
        for (int i = 0; i < 4; ++i) { ar[i] = br0; az[i] = bz0; ani[i] = bni; anh[i] = bnh; }

        // i-part: x(96 = prev rows h-1,h,h+1 contiguous in bufPrev) @ Wih^T
#pragma unroll 8
        for (int kq = 0; kq < 24; ++kq) {
            float4 wr = *(const float4*)&sWih[(c)      * 100 + kq * 4];
            float4 wz = *(const float4*)&sWih[(32 + c) * 100 + kq * 4];
            float4 wn = *(const float4*)&sWih[(64 + c) * 100 + kq * 4];
#pragma unroll
            for (int i = 0; i < 4; ++i) {
                float4 xv = *(const float4*)&bufPrev[(rq * 4 + i) * 32 + kq * 4];
                ar[i]  = fmaf(xv.x, wr.x, fmaf(xv.y, wr.y, fmaf(xv.z, wr.z, fmaf(xv.w, wr.w, ar[i]))));
                az[i]  = fmaf(xv.x, wz.x, fmaf(xv.y, wz.y, fmaf(xv.z, wz.z, fmaf(xv.w, wz.w, az[i]))));
                ani[i] = fmaf(xv.x, wn.x, fmaf(xv.y, wn.y, fmaf(xv.z, wn.z, fmaf(xv.w, wn.w, ani[i]))));
            }
        }
        // h-part: cur col (32) @ Whh^T
#pragma unroll
        for (int kq = 0; kq < 8; ++kq) {
            float4 wr = *(const float4*)&sWhh[(c)      * 36 + kq * 4];
            float4 wz = *(const float4*)&sWhh[(32 + c) * 36 + kq * 4];
            float4 wn = *(const float4*)&sWhh[(64 + c) * 36 + kq * 4];
#pragma unroll
            for (int i = 0; i < 4; ++i) {
                float4 hv = *(const float4*)&sCur[(rq * 4 + i) * 32 + kq * 4];
                ar[i]  = fmaf(hv.x, wr.x, fmaf(hv.y, wr.y, fmaf(hv.z, wr.z, fmaf(hv.w, wr.w, ar[i]))));
                az[i]  = fmaf(hv.x, wz.x, fmaf(hv.y, wz.y, fmaf(hv.z, wz.z, fmaf(hv.w, wz.w, az[i]))));
                anh[i] = fmaf(hv.x, wn.x, fmaf(hv.y, wn.y, fmaf(hv.z, wn.z, fmaf(hv.w, wn.w, anh[i]))));
            }
        }

        float outv[4];
#pragma unroll
        for (int i = 0; i < 4; ++i) {
            float rg = sigmoid_fast(ar[i]);
            float zg = sigmoid_fast(az[i]);
            float ng = tanh_fast(fmaf(rg, anh[i], ani[i]));
            float cv = sCur[(rq * 4 + i) * 32 + c];
            outv[i]  = fmaf(ng - cv, zg, cv);   // n*z + cur*(1-z)
        }

        // write own rows into the other buffer + global (double-buffered: no
        // barrier needed here — next step's barrier orders all consumers)
#pragma unroll
        for (int i = 0; i < 4; ++i) {
            int r = rq * 4 + i;
            bufCur[(1 + r) * 32 + c] = outv[i];
            __stcg(&g_Yt[((size_t)(w * 8 + b) * 512 + (h0 + r)) * 32 + c], outv[i]);
        }
        // Edge warps publish their rows immediately (release orders the __stcg
        // data stores before the flag in L2):
        if (rq == 0) {                    // warp 0 stored row 0
            __syncwarp();
            if (c == 0) st_rel(&g_lo[beta], sBase + (unsigned)(w + 1));
        } else if (rq == 7) {             // warp 7 stored row 31
            __syncwarp();
            if (c == 0) st_rel(&g_hi[beta], sBase + (unsigned)(w + 1));
        }
    }
}

// ---------------------------------------------------------------------------
extern "C" void kernel_launch(void* const* d_in, const int* in_sizes, int n_in,
                              void* d_out, int out_size) {
    const float* states = (const float*)d_in[0];
    const float* wih    = (const float*)d_in[1];
    const float* bih    = (const float*)d_in[2];
    const float* whh    = (const float*)d_in[3];
    const float* bhh    = (const float*)d_in[4];
    float* out = (float*)d_out;

    cudaFuncSetAttribute(scan_kernel, cudaFuncAttributeMaxDynamicSharedMemorySize,
                         SM_FLOATS * (int)sizeof(float));

    dim3 tgrid(W_DIM / 32, H_DIM, B_DIM);
    transpose_in_kernel<<<tgrid, 256>>>(states);
    scan_kernel<<<NBLK, NTHR, SM_FLOATS * sizeof(float)>>>(wih, bih, whh, bhh);
    transpose_out_kernel<<<tgrid, 256>>>(out);
}

// round 6
// speedup vs baseline: 1.3472x; 1.2451x over previous
#include <cuda_runtime.h>

// Problem constants
#define W_DIM 512
#define H_DIM 512
#define B_DIM 8
#define C_DIM 32
#define NBLK  128           // 8 batches * 16 row-tiles of 32 rows
#define NTHR  256

// Scratch: transposed input/output in (W, B, H, C) layout, C contiguous.
__device__ float    g_Xt[W_DIM * B_DIM * H_DIM * C_DIM];   // 256 MB
__device__ float    g_Yt[W_DIM * B_DIM * H_DIM * C_DIM];   // 256 MB
__device__ unsigned g_progress[NBLK];                       // monotonic counters

// ---- fast math -------------------------------------------------------------
__device__ __forceinline__ float tanh_fast(float x) {
    float y; asm("tanh.approx.f32 %0, %1;" : "=f"(y) : "f"(x)); return y;
}
__device__ __forceinline__ float sigmoid_fast(float x) {
    return fmaf(0.5f, tanh_fast(0.5f * x), 0.5f);
}

// ---------------------------------------------------------------------------
// Transpose (B,C,H,W) -> (W,B,H,C)
// ---------------------------------------------------------------------------
__global__ __launch_bounds__(256) void transpose_in_kernel(const float* __restrict__ states) {
    __shared__ float tile[32][33];
    const int wt = blockIdx.x, h = blockIdx.y, b = blockIdx.z;
    const int w0 = wt * 32;
    const int t  = threadIdx.x;
    const int lo = t & 31, g = t >> 5;
#pragma unroll
    for (int i = 0; i < 4; ++i) {
        int cc = g * 4 + i;
        tile[cc][lo] = states[((size_t)(b * 32 + cc) * 512 + h) * 512 + (w0 + lo)];
    }
    __syncthreads();
#pragma unroll
    for (int i = 0; i < 4; ++i) {
        int ww = g * 4 + i;
        g_Xt[((size_t)((w0 + ww) * 8 + b) * 512 + h) * 32 + lo] = tile[lo][ww];
    }
}

// ---------------------------------------------------------------------------
// Transpose (W,B,H,C) -> (B,C,H,W)
// ---------------------------------------------------------------------------
__global__ __launch_bounds__(256) void transpose_out_kernel(float* __restrict__ out) {
    __shared__ float tile[32][33];
    const int wt = blockIdx.x, h = blockIdx.y, b = blockIdx.z;
    const int w0 = wt * 32;
    const int t  = threadIdx.x;
    const int lo = t & 31, g = t >> 5;
#pragma unroll
    for (int i = 0; i < 4; ++i) {
        int ww = g * 4 + i;
        tile[ww][lo] = g_Yt[((size_t)((w0 + ww) * 8 + b) * 512 + h) * 32 + lo];
    }
    __syncthreads();
#pragma unroll
    for (int i = 0; i < 4; ++i) {
        int cc = g * 4 + i;
        out[((size_t)(b * 32 + cc) * 512 + h) * 512 + (w0 + lo)] = tile[lo][cc];
    }
}

// ---------------------------------------------------------------------------
// Persistent scan kernel — R1-proven flag protocol (threadfence + atomicExch
// producer; atomicAdd poll + __ldcg consumer), with:
//   * input column prefetched one step ahead (DRAM latency off critical path)
//   * double-buffered prev-column tile (no WAR barrier; 2 barriers/step)
//   * tanh.approx epilogue
//
// smem layout (floats):
//   sWih  : 96 x 100 (stride % 32 == 4 -> conflict-free float4) = 9600
//   sWhh  : 96 x 36                                             = 3456
//   buf0  : 34 x 32  (prev column + 2 halo rows)                = 1088
//   buf1  : 34 x 32                                             = 1088
//   sCur0 : 32 x 32  (current input column)                     = 1024
//   sCur1 : 32 x 32                                             = 1024
// total 17280 floats = 69120 bytes (dynamic)
// ---------------------------------------------------------------------------
#define SM_WIH  0
#define SM_WHH  (SM_WIH + 96 * 100)
#define SM_BUF0 (SM_WHH + 96 * 36)
#define SM_BUF1 (SM_BUF0 + 34 * 32)
#define SM_CUR0 (SM_BUF1 + 34 * 32)
#define SM_CUR1 (SM_CUR0 + 32 * 32)
#define SM_FLOATS (SM_CUR1 + 32 * 32)

__global__ __launch_bounds__(NTHR, 1) void scan_kernel(
    const float* __restrict__ Wih, const float* __restrict__ bih,
    const float* __restrict__ Whh, const float* __restrict__ bhh)
{
    extern __shared__ float sm[];
    float* sWih = sm + SM_WIH;
    float* sWhh = sm + SM_WHH;
    float* bufA[2] = { sm + SM_BUF0, sm + SM_BUF1 };
    float* curA[2] = { sm + SM_CUR0, sm + SM_CUR1 };
    __shared__ unsigned sBase;

    const int tid  = threadIdx.x;
    const int beta = blockIdx.x;
    const int b    = beta >> 4;
    const int tile = beta & 15;
    const int h0   = tile * 32;
    const int c    = tid & 31;        // channel
    const int rq   = tid >> 5;        // warp id = row quad: rows rq*4 .. rq*4+3

    if (tid == 0) sBase = atomicAdd(&g_progress[beta], 0u);

    for (int i = tid; i < 96 * 96; i += NTHR) sWih[(i / 96) * 100 + (i % 96)] = Wih[i];
    for (int i = tid; i < 96 * 32; i += NTHR) sWhh[(i / 32) * 36  + (i % 32)] = Whh[i];

    const float br0 = bih[c]      + bhh[c];
    const float bz0 = bih[32 + c] + bhh[32 + c];
    const float bni = bih[64 + c];
    const float bnh = bhh[64 + c];

    // zero halo slots of both buffers (edge tiles never overwrite them)
    if (tid < 32) { bufA[0][tid] = 0.0f; bufA[1][tid] = 0.0f; }
    else if (tid < 64) { bufA[0][33 * 32 + (tid - 32)] = 0.0f; bufA[1][33 * 32 + (tid - 32)] = 0.0f; }
    __syncthreads();

    // Publish column 0 = input column 0 (identity passthrough) into buf0
    for (int i = tid; i < 1024; i += NTHR) {
        int r = i >> 5, cc = i & 31;
        size_t gi = ((size_t)b * 512 + (h0 + r)) * 32 + cc;   // w = 0
        float v = g_Xt[gi];
        bufA[0][(1 + r) * 32 + cc] = v;
        g_Yt[gi] = v;
    }
    __threadfence();
    __syncthreads();
    if (tid == 0) atomicExch(&g_progress[beta], sBase + 1);

    // Prefetch input column w=1 into registers
    float4 xnext = *(const float4*)&g_Xt[((size_t)(1 * 8 + b) * 512 + h0) * 32 + tid * 4];

    for (int w = 1; w < W_DIM; ++w) {
        float* bufPrev = bufA[(w - 1) & 1];   // holds column w-1 (+ halos)
        float* bufCur  = bufA[w & 1];         // receives column w
        float* sCur    = curA[w & 1];         // current input column

        // Store the prefetched input column; immediately issue next prefetch
        ((float4*)sCur)[tid] = xnext;
        if (w + 1 < W_DIM)
            xnext = *(const float4*)&g_Xt[((size_t)((w + 1) * 8 + b) * 512 + h0) * 32 + tid * 4];

        // Warps 0/1: wait for +-1 neighbor (R1-proven atomic poll), fetch halos
        if (tid < 64) {
            const bool down = tid < 32;
            const int  lane = tid & 31;
            const bool valid = down ? (tile > 0) : (tile < 15);
            if (valid) {
                const int nb = down ? beta - 1 : beta + 1;
                if (lane == 0) {
                    const unsigned tgt = sBase + (unsigned)w;
                    while (atomicAdd(&g_progress[nb], 0u) < tgt) { }
                }
                __syncwarp(0xFFFFFFFFu);
                const int hh = down ? (h0 - 1) : (h0 + 32);
                float v = __ldcg(&g_Yt[((size_t)((w - 1) * 8 + b) * 512 + hh) * 32 + lane]);
                bufPrev[(down ? 0 : 33) * 32 + lane] = v;
            }
        }
        __syncthreads();   // barrier #1: halos + sCur visible to all

        // ---- compute: 4 rows x 1 channel per thread -----------------------
        float ar[4], az[4], ani[4], anh[4];
#pragma unroll
        for (int i = 0; i < 4; ++i) { ar[i] = br0; az[i] = bz0; ani[i] = bni; anh[i] = bnh; }

        // i-part: x(96 = prev rows h-1,h,h+1 contiguous in bufPrev) @ Wih^T
#pragma unroll 8
        for (int kq = 0; kq < 24; ++kq) {
            float4 wr = *(const float4*)&sWih[(c)      * 100 + kq * 4];
            float4 wz = *(const float4*)&sWih[(32 + c) * 100 + kq * 4];
            float4 wn = *(const float4*)&sWih[(64 + c) * 100 + kq * 4];
#pragma unroll
            for (int i = 0; i < 4; ++i) {
                float4 xv = *(const float4*)&bufPrev[(rq * 4 + i) * 32 + kq * 4];
                ar[i]  = fmaf(xv.x, wr.x, fmaf(xv.y, wr.y, fmaf(xv.z, wr.z, fmaf(xv.w, wr.w, ar[i]))));
                az[i]  = fmaf(xv.x, wz.x, fmaf(xv.y, wz.y, fmaf(xv.z, wz.z, fmaf(xv.w, wz.w, az[i]))));
                ani[i] = fmaf(xv.x, wn.x, fmaf(xv.y, wn.y, fmaf(xv.z, wn.z, fmaf(xv.w, wn.w, ani[i]))));
            }
        }
        // h-part: cur col (32) @ Whh^T
#pragma unroll
        for (int kq = 0; kq < 8; ++kq) {
            float4 wr = *(const float4*)&sWhh[(c)      * 36 + kq * 4];
            float4 wz = *(const float4*)&sWhh[(32 + c) * 36 + kq * 4];
            float4 wn = *(const float4*)&sWhh[(64 + c) * 36 + kq * 4];
#pragma unroll
            for (int i = 0; i < 4; ++i) {
                float4 hv = *(const float4*)&sCur[(rq * 4 + i) * 32 + kq * 4];
                ar[i]  = fmaf(hv.x, wr.x, fmaf(hv.y, wr.y, fmaf(hv.z, wr.z, fmaf(hv.w, wr.w, ar[i]))));
                az[i]  = fmaf(hv.x, wz.x, fmaf(hv.y, wz.y, fmaf(hv.z, wz.z, fmaf(hv.w, wz.w, az[i]))));
                anh[i] = fmaf(hv.x, wn.x, fmaf(hv.y, wn.y, fmaf(hv.z, wn.z, fmaf(hv.w, wn.w, anh[i]))));
            }
        }

        float outv[4];
#pragma unroll
        for (int i = 0; i < 4; ++i) {
            float rg = sigmoid_fast(ar[i]);
            float zg = sigmoid_fast(az[i]);
            float ng = tanh_fast(fmaf(rg, anh[i], ani[i]));
            float cv = sCur[(rq * 4 + i) * 32 + c];
            outv[i]  = fmaf(ng - cv, zg, cv);   // n*z + cur*(1-z)
        }

        // write own rows into the OTHER buffer (no WAR hazard) + global
#pragma unroll
        for (int i = 0; i < 4; ++i) {
            int r = rq * 4 + i;
            bufCur[(1 + r) * 32 + c] = outv[i];
            g_Yt[((size_t)(w * 8 + b) * 512 + (h0 + r)) * 32 + c] = outv[i];
        }
        __threadfence();
        __syncthreads();   // barrier #2: all stores done before flag
        if (tid == 0) atomicExch(&g_progress[beta], sBase + (unsigned)(w + 1));
    }
}

// ---------------------------------------------------------------------------
extern "C" void kernel_launch(void* const* d_in, const int* in_sizes, int n_in,
                              void* d_out, int out_size) {
    const float* states = (const float*)d_in[0];
    const float* wih    = (const float*)d_in[1];
    const float* bih    = (const float*)d_in[2];
    const float* whh    = (const float*)d_in[3];
    const float* bhh    = (const float*)d_in[4];
    float* out = (float*)d_out;

    cudaFuncSetAttribute(scan_kernel, cudaFuncAttributeMaxDynamicSharedMemorySize,
                         SM_FLOATS * (int)sizeof(float));

    dim3 tgrid(W_DIM / 32, H_DIM, B_DIM);
    transpose_in_kernel<<<tgrid, 256>>>(states);
    scan_kernel<<<NBLK, NTHR, SM_FLOATS * sizeof(float)>>>(wih, bih, whh, bhh);
    transpose_out_kernel<<<tgrid, 256>>>(out);
}

// round 7
// speedup vs baseline: 1.5435x; 1.1457x over previous
#include <cuda_runtime.h>

// Problem constants
#define W_DIM 512
#define H_DIM 512
#define B_DIM 8
#define C_DIM 32
#define NBLK  128           // 8 batches * 16 row-tiles of 32 rows
#define NTHR  256

// Scratch: transposed input/output in (W, B, H, C) layout, C contiguous.
__device__ float    g_Xt[W_DIM * B_DIM * H_DIM * C_DIM];   // 256 MB
__device__ float    g_Yt[W_DIM * B_DIM * H_DIM * C_DIM];   // 256 MB
__device__ unsigned g_progress[NBLK];                       // monotonic counters

// ---- fast math -------------------------------------------------------------
__device__ __forceinline__ float tanh_fast(float x) {
    float y; asm("tanh.approx.f32 %0, %1;" : "=f"(y) : "f"(x)); return y;
}
__device__ __forceinline__ float sigmoid_fast(float x) {
    return fmaf(0.5f, tanh_fast(0.5f * x), 0.5f);
}

// ---------------------------------------------------------------------------
// Transpose (B,C,H,W) -> (W,B,H,C)
// ---------------------------------------------------------------------------
__global__ __launch_bounds__(256) void transpose_in_kernel(const float* __restrict__ states) {
    __shared__ float tile[32][33];
    const int wt = blockIdx.x, h = blockIdx.y, b = blockIdx.z;
    const int w0 = wt * 32;
    const int t  = threadIdx.x;
    const int lo = t & 31, g = t >> 5;
#pragma unroll
    for (int i = 0; i < 4; ++i) {
        int cc = g * 4 + i;
        tile[cc][lo] = states[((size_t)(b * 32 + cc) * 512 + h) * 512 + (w0 + lo)];
    }
    __syncthreads();
#pragma unroll
    for (int i = 0; i < 4; ++i) {
        int ww = g * 4 + i;
        g_Xt[((size_t)((w0 + ww) * 8 + b) * 512 + h) * 32 + lo] = tile[lo][ww];
    }
}

// ---------------------------------------------------------------------------
// Transpose (W,B,H,C) -> (B,C,H,W)
// ---------------------------------------------------------------------------
__global__ __launch_bounds__(256) void transpose_out_kernel(float* __restrict__ out) {
    __shared__ float tile[32][33];
    const int wt = blockIdx.x, h = blockIdx.y, b = blockIdx.z;
    const int w0 = wt * 32;
    const int t  = threadIdx.x;
    const int lo = t & 31, g = t >> 5;
#pragma unroll
    for (int i = 0; i < 4; ++i) {
        int ww = g * 4 + i;
        tile[ww][lo] = g_Yt[((size_t)((w0 + ww) * 8 + b) * 512 + h) * 32 + lo];
    }
    __syncthreads();
#pragma unroll
    for (int i = 0; i < 4; ++i) {
        int cc = g * 4 + i;
        out[((size_t)(b * 32 + cc) * 512 + h) * 512 + (w0 + lo)] = tile[lo][cc];
    }
}

// ---------------------------------------------------------------------------
// Persistent scan kernel — EXACT R1 structure and sync protocol (the only
// variant that benched 2994us): single sHs buffer, 3 barriers/step,
// __threadfence + atomicExch producer, atomicAdd-poll consumer, __ldcg halo.
// Only two non-structural changes vs R1:
//   (1) input column prefetched into registers one step ahead
//   (2) tanh.approx epilogue
//
// smem layout (floats):
//   sWih : 96 x 100 (stride % 32 == 4 -> conflict-free float4) = 9600
//   sWhh : 96 x 36                                             = 3456
//   sHs  : 34 x 32 (halo + own prev column)                    = 1088
//   sCur : 32 x 32 (current input column)                      = 1024
// total 15168 floats = 60672 bytes (dynamic)
// ---------------------------------------------------------------------------
#define SM_WIH 0
#define SM_WHH (SM_WIH + 96 * 100)
#define SM_HS  (SM_WHH + 96 * 36)
#define SM_CUR (SM_HS + 34 * 32)
#define SM_FLOATS (SM_CUR + 32 * 32)

__global__ __launch_bounds__(NTHR, 1) void scan_kernel(
    const float* __restrict__ Wih, const float* __restrict__ bih,
    const float* __restrict__ Whh, const float* __restrict__ bhh)
{
    extern __shared__ float sm[];
    float* sWih = sm + SM_WIH;
    float* sWhh = sm + SM_WHH;
    float* sHs  = sm + SM_HS;
    float* sCur = sm + SM_CUR;
    __shared__ unsigned sBase;

    const int tid  = threadIdx.x;
    const int beta = blockIdx.x;
    const int b    = beta >> 4;
    const int tile = beta & 15;
    const int h0   = tile * 32;
    const int c    = tid & 31;        // channel
    const int rq   = tid >> 5;        // row quad (0..7): rows rq*4 .. rq*4+3

    if (tid == 0) sBase = atomicAdd(&g_progress[beta], 0u);

    for (int i = tid; i < 96 * 96; i += NTHR) sWih[(i / 96) * 100 + (i % 96)] = Wih[i];
    for (int i = tid; i < 96 * 32; i += NTHR) sWhh[(i / 32) * 36  + (i % 32)] = Whh[i];

    const float br0 = bih[c]      + bhh[c];
    const float bz0 = bih[32 + c] + bhh[32 + c];
    const float bni = bih[64 + c];
    const float bnh = bhh[64 + c];
    __syncthreads();

    // Publish column 0 = input column 0 (identity passthrough)
    for (int i = tid; i < 1024; i += NTHR) {
        int r = i >> 5, cc = i & 31;
        size_t gi = ((size_t)b * 512 + (h0 + r)) * 32 + cc;   // w = 0
        float v = g_Xt[gi];
        sHs[(1 + r) * 32 + cc] = v;
        g_Yt[gi] = v;
    }
    __threadfence();
    __syncthreads();
    if (tid == 0) atomicExch(&g_progress[beta], sBase + 1);

    // Prefetch input column w=1 into registers (off the critical path)
    float4 xnext = *(const float4*)&g_Xt[((size_t)(1 * 8 + b) * 512 + h0) * 32 + tid * 4];

    for (int w = 1; w < W_DIM; ++w) {
        // Store the prefetched column; immediately issue next step's prefetch
        ((float4*)sCur)[tid] = xnext;
        if (w + 1 < W_DIM)
            xnext = *(const float4*)&g_Xt[((size_t)((w + 1) * 8 + b) * 512 + h0) * 32 + tid * 4];

        // Wait for +-1 neighbor blocks to have published column w-1
        if (tid < 2) {
            int  nb    = (tid == 0) ? beta - 1 : beta + 1;
            bool valid = (tid == 0) ? (tile > 0) : (tile < 15);
            if (valid) {
                unsigned tgt = sBase + (unsigned)w;
                while (atomicAdd(&g_progress[nb], 0u) < tgt) { }
            }
        }
        __syncthreads();

        // Halo rows (h0-1, h0+32) of previous output column; L2-only loads
        if (tid < 32) {
            float v = 0.0f;
            if (tile > 0)
                v = __ldcg(&g_Yt[((size_t)((w - 1) * 8 + b) * 512 + (h0 - 1)) * 32 + tid]);
            sHs[tid] = v;
        } else if (tid < 64) {
            int cc = tid - 32;
            float v = 0.0f;
            if (tile < 15)
                v = __ldcg(&g_Yt[((size_t)((w - 1) * 8 + b) * 512 + (h0 + 32)) * 32 + cc]);
            sHs[33 * 32 + cc] = v;
        }
        __syncthreads();

        // ---- compute: 4 rows x 1 channel per thread -----------------------
        float ar[4], az[4], ani[4], anh[4];
#pragma unroll
        for (int i = 0; i < 4; ++i) { ar[i] = br0; az[i] = bz0; ani[i] = bni; anh[i] = bnh; }

        // i-part: x(96, = prev rows h-1,h,h+1 contiguous in sHs) @ Wih^T
#pragma unroll 8
        for (int kq = 0; kq < 24; ++kq) {
            float4 wr = *(const float4*)&sWih[(c)      * 100 + kq * 4];
            float4 wz = *(const float4*)&sWih[(32 + c) * 100 + kq * 4];
            float4 wn = *(const float4*)&sWih[(64 + c) * 100 + kq * 4];
#pragma unroll
            for (int i = 0; i < 4; ++i) {
                float4 xv = *(const float4*)&sHs[(rq * 4 + i) * 32 + kq * 4];
                ar[i]  = fmaf(xv.x, wr.x, fmaf(xv.y, wr.y, fmaf(xv.z, wr.z, fmaf(xv.w, wr.w, ar[i]))));
                az[i]  = fmaf(xv.x, wz.x, fmaf(xv.y, wz.y, fmaf(xv.z, wz.z, fmaf(xv.w, wz.w, az[i]))));
                ani[i] = fmaf(xv.x, wn.x, fmaf(xv.y, wn.y, fmaf(xv.z, wn.z, fmaf(xv.w, wn.w, ani[i]))));
            }
        }
        // h-part: cur col (32) @ Whh^T
#pragma unroll
        for (int kq = 0; kq < 8; ++kq) {
            float4 wr = *(const float4*)&sWhh[(c)      * 36 + kq * 4];
            float4 wz = *(const float4*)&sWhh[(32 + c) * 36 + kq * 4];
            float4 wn = *(const float4*)&sWhh[(64 + c) * 36 + kq * 4];
#pragma unroll
            for (int i = 0; i < 4; ++i) {
                float4 hv = *(const float4*)&sCur[(rq * 4 + i) * 32 + kq * 4];
                ar[i]  = fmaf(hv.x, wr.x, fmaf(hv.y, wr.y, fmaf(hv.z, wr.z, fmaf(hv.w, wr.w, ar[i]))));
                az[i]  = fmaf(hv.x, wz.x, fmaf(hv.y, wz.y, fmaf(hv.z, wz.z, fmaf(hv.w, wz.w, az[i]))));
                anh[i] = fmaf(hv.x, wn.x, fmaf(hv.y, wn.y, fmaf(hv.z, wn.z, fmaf(hv.w, wn.w, anh[i]))));
            }
        }

        float outv[4];
#pragma unroll
        for (int i = 0; i < 4; ++i) {
            float rg = sigmoid_fast(ar[i]);
            float zg = sigmoid_fast(az[i]);
            float ng = tanh_fast(fmaf(rg, anh[i], ani[i]));
            float cv = sCur[(rq * 4 + i) * 32 + c];
            outv[i]  = fmaf(ng - cv, zg, cv);   // n*z + cur*(1-z)
        }

        __syncthreads();   // all reads of sHs done before overwriting
#pragma unroll
        for (int i = 0; i < 4; ++i) {
            int r = rq * 4 + i;
            sHs[(1 + r) * 32 + c] = outv[i];
            g_Yt[((size_t)(w * 8 + b) * 512 + (h0 + r)) * 32 + c] = outv[i];
        }
        __threadfence();
        __syncthreads();
        if (tid == 0) atomicExch(&g_progress[beta], sBase + (unsigned)(w + 1));
    }
}

// ---------------------------------------------------------------------------
extern "C" void kernel_launch(void* const* d_in, const int* in_sizes, int n_in,
                              void* d_out, int out_size) {
    const float* states = (const float*)d_in[0];
    const float* wih    = (const float*)d_in[1];
    const float* bih    = (const float*)d_in[2];
    const float* whh    = (const float*)d_in[3];
    const float* bhh    = (const float*)d_in[4];
    float* out = (float*)d_out;

    cudaFuncSetAttribute(scan_kernel, cudaFuncAttributeMaxDynamicSharedMemorySize,
                         SM_FLOATS * (int)sizeof(float));

    dim3 tgrid(W_DIM / 32, H_DIM, B_DIM);
    transpose_in_kernel<<<tgrid, 256>>>(states);
    scan_kernel<<<NBLK, NTHR, SM_FLOATS * sizeof(float)>>>(wih, bih, whh, bhh);
    transpose_out_kernel<<<tgrid, 256>>>(out);
}

// round 8
// speedup vs baseline: 2.0607x; 1.3351x over previous
#include <cuda_runtime.h>

// Problem constants
#define W_DIM 512
#define H_DIM 512
#define B_DIM 8
#define C_DIM 32
#define NBLK  128           // 8 batches * 16 row-tiles of 32 rows
#define NTHR  256

// Scratch: transposed input/output in (W, B, H, C) layout, C contiguous.
__device__ float    g_Xt[W_DIM * B_DIM * H_DIM * C_DIM];   // 256 MB
__device__ float    g_Yt[W_DIM * B_DIM * H_DIM * C_DIM];   // 256 MB
__device__ unsigned g_progress[NBLK];                       // monotonic counters

// ---- fast math -------------------------------------------------------------
__device__ __forceinline__ float tanh_fast(float x) {
    float y; asm("tanh.approx.f32 %0, %1;" : "=f"(y) : "f"(x)); return y;
}
__device__ __forceinline__ float sigmoid_fast(float x) {
    return fmaf(0.5f, tanh_fast(0.5f * x), 0.5f);
}

// ---------------------------------------------------------------------------
// Transpose (B,C,H,W) -> (W,B,H,C)
// ---------------------------------------------------------------------------
__global__ __launch_bounds__(256) void transpose_in_kernel(const float* __restrict__ states) {
    __shared__ float tile[32][33];
    const int wt = blockIdx.x, h = blockIdx.y, b = blockIdx.z;
    const int w0 = wt * 32;
    const int t  = threadIdx.x;
    const int lo = t & 31, g = t >> 5;
#pragma unroll
    for (int i = 0; i < 4; ++i) {
        int cc = g * 4 + i;
        tile[cc][lo] = states[((size_t)(b * 32 + cc) * 512 + h) * 512 + (w0 + lo)];
    }
    __syncthreads();
#pragma unroll
    for (int i = 0; i < 4; ++i) {
        int ww = g * 4 + i;
        g_Xt[((size_t)((w0 + ww) * 8 + b) * 512 + h) * 32 + lo] = tile[lo][ww];
    }
}

// ---------------------------------------------------------------------------
// Transpose (W,B,H,C) -> (B,C,H,W)
// ---------------------------------------------------------------------------
__global__ __launch_bounds__(256) void transpose_out_kernel(float* __restrict__ out) {
    __shared__ float tile[32][33];
    const int wt = blockIdx.x, h = blockIdx.y, b = blockIdx.z;
    const int w0 = wt * 32;
    const int t  = threadIdx.x;
    const int lo = t & 31, g = t >> 5;
#pragma unroll
    for (int i = 0; i < 4; ++i) {
        int ww = g * 4 + i;
        tile[ww][lo] = g_Yt[((size_t)((w0 + ww) * 8 + b) * 512 + h) * 32 + lo];
    }
    __syncthreads();
#pragma unroll
    for (int i = 0; i < 4; ++i) {
        int cc = g * 4 + i;
        out[((size_t)(b * 32 + cc) * 512 + h) * 512 + (w0 + lo)] = tile[lo][cc];
    }
}

// ---------------------------------------------------------------------------
// smem layout (floats) — all offsets compile-time constants
//   sWih : 96 x 100 (stride % 32 == 4 -> conflict-free float4) = 9600
//   sWhh : 96 x 36                                             = 3456
//   bufA : 34 x 32  (column + 2 halo slots)                    = 1088
//   bufB : 34 x 32                                             = 1088
//   sCur : 32 x 32  (input column; warp-local, single buffer)  = 1024
// total 16256 floats = 65024 bytes (dynamic)
// ---------------------------------------------------------------------------
#define SM_WIH  0
#define SM_WHH  (SM_WIH + 96 * 100)
#define SM_BUFA (SM_WHH + 96 * 36)
#define SM_BUFB (SM_BUFA + 34 * 32)
#define SM_CUR  (SM_BUFB + 34 * 32)
#define SM_FLOATS (SM_CUR + 32 * 32)

// ---------------------------------------------------------------------------
// One scan step. PREV/NEXT are compile-time smem offsets (no runtime pointer
// select). Sync per step: __syncwarp (warp-local sCur/halo) + ONE
// __syncthreads (interior tile handoff + pre-flag store drain, R1 protocol).
// Halo slots are fetched by the warp that consumes them (warp 0 -> slot 0,
// warp 7 -> slot 33), so neighbor poll latency is off the other warps' path.
// ---------------------------------------------------------------------------
template<int PREV, int NEXT>
__device__ __forceinline__ void gru_step(
    float* __restrict__ sm, int w, float4& xnext,
    int tid, int b, int tile, int h0, int c, int rq, int beta, unsigned sBase,
    float br0, float bz0, float bni, float bnh)
{
    // Own-row input-column store from prefetch register; issue next prefetch
    ((float4*)(sm + SM_CUR))[tid] = xnext;
    if (w + 1 < W_DIM)
        xnext = *(const float4*)&g_Xt[((size_t)((w + 1) * 8 + b) * 512 + h0) * 32 + tid * 4];

    // Edge warps fetch their own halo row of column w-1
    if (rq == 0) {
        if (tile > 0) {
            if ((tid & 31) == 0) {
                const unsigned tgt = sBase + (unsigned)w;
                while (atomicAdd(&g_progress[beta - 1], 0u) < tgt) { }
            }
            __syncwarp();
            float v = __ldcg(&g_Yt[((size_t)((w - 1) * 8 + b) * 512 + (h0 - 1)) * 32 + (tid & 31)]);
            sm[PREV + (tid & 31)] = v;                     // slot 0
        }
    } else if (rq == 7) {
        if (tile < 15) {
            if ((tid & 31) == 0) {
                const unsigned tgt = sBase + (unsigned)w;
                while (atomicAdd(&g_progress[beta + 1], 0u) < tgt) { }
            }
            __syncwarp();
            float v = __ldcg(&g_Yt[((size_t)((w - 1) * 8 + b) * 512 + (h0 + 32)) * 32 + (tid & 31)]);
            sm[PREV + 33 * 32 + (tid & 31)] = v;           // slot 33
        }
    }
    __syncwarp();   // cross-lane visibility of sCur rows + own halo slot

    // ---- compute: 4 rows x 1 channel per thread ---------------------------
    float ar[4], az[4], ani[4], anh[4];
#pragma unroll
    for (int i = 0; i < 4; ++i) { ar[i] = br0; az[i] = bz0; ani[i] = bni; anh[i] = bnh; }

    // i-part: x(96 = prev rows h-1,h,h+1 contiguous in buf slots) @ Wih^T
#pragma unroll 8
    for (int kq = 0; kq < 24; ++kq) {
        float4 wr = *(const float4*)&sm[SM_WIH + (c)      * 100 + kq * 4];
        float4 wz = *(const float4*)&sm[SM_WIH + (32 + c) * 100 + kq * 4];
        float4 wn = *(const float4*)&sm[SM_WIH + (64 + c) * 100 + kq * 4];
#pragma unroll
        for (int i = 0; i < 4; ++i) {
            float4 xv = *(const float4*)&sm[PREV + (rq * 4 + i) * 32 + kq * 4];
            ar[i]  = fmaf(xv.x, wr.x, fmaf(xv.y, wr.y, fmaf(xv.z, wr.z, fmaf(xv.w, wr.w, ar[i]))));
            az[i]  = fmaf(xv.x, wz.x, fmaf(xv.y, wz.y, fmaf(xv.z, wz.z, fmaf(xv.w, wz.w, az[i]))));
            ani[i] = fmaf(xv.x, wn.x, fmaf(xv.y, wn.y, fmaf(xv.z, wn.z, fmaf(xv.w, wn.w, ani[i]))));
        }
    }
    // h-part: cur col (32) @ Whh^T
#pragma unroll
    for (int kq = 0; kq < 8; ++kq) {
        float4 wr = *(const float4*)&sm[SM_WHH + (c)      * 36 + kq * 4];
        float4 wz = *(const float4*)&sm[SM_WHH + (32 + c) * 36 + kq * 4];
        float4 wn = *(const float4*)&sm[SM_WHH + (64 + c) * 36 + kq * 4];
#pragma unroll
        for (int i = 0; i < 4; ++i) {
            float4 hv = *(const float4*)&sm[SM_CUR + (rq * 4 + i) * 32 + kq * 4];
            ar[i]  = fmaf(hv.x, wr.x, fmaf(hv.y, wr.y, fmaf(hv.z, wr.z, fmaf(hv.w, wr.w, ar[i]))));
            az[i]  = fmaf(hv.x, wz.x, fmaf(hv.y, wz.y, fmaf(hv.z, wz.z, fmaf(hv.w, wz.w, az[i]))));
            anh[i] = fmaf(hv.x, wn.x, fmaf(hv.y, wn.y, fmaf(hv.z, wn.z, fmaf(hv.w, wn.w, anh[i]))));
        }
    }

    float outv[4];
#pragma unroll
    for (int i = 0; i < 4; ++i) {
        float rg = sigmoid_fast(ar[i]);
        float zg = sigmoid_fast(az[i]);
        float ng = tanh_fast(fmaf(rg, anh[i], ani[i]));
        float cv = sm[SM_CUR + (rq * 4 + i) * 32 + c];
        outv[i]  = fmaf(ng - cv, zg, cv);   // n*z + cur*(1-z)
    }

    // write own rows into the NEXT buffer (WAR-free) + global output
#pragma unroll
    for (int i = 0; i < 4; ++i) {
        int r = rq * 4 + i;
        sm[NEXT + (1 + r) * 32 + c] = outv[i];
        g_Yt[((size_t)(w * 8 + b) * 512 + (h0 + r)) * 32 + c] = outv[i];
    }
    __threadfence();
    __syncthreads();   // the ONLY block barrier: tile handoff + store drain
    if (tid == 0) atomicExch(&g_progress[beta], sBase + (unsigned)(w + 1));
}

__global__ __launch_bounds__(NTHR, 1) void scan_kernel(
    const float* __restrict__ Wih, const float* __restrict__ bih,
    const float* __restrict__ Whh, const float* __restrict__ bhh)
{
    extern __shared__ float sm[];
    __shared__ unsigned sBaseSh;

    const int tid  = threadIdx.x;
    const int beta = blockIdx.x;
    const int b    = beta >> 4;
    const int tile = beta & 15;
    const int h0   = tile * 32;
    const int c    = tid & 31;        // channel
    const int rq   = tid >> 5;        // warp id = row quad: rows rq*4 .. rq*4+3

    if (tid == 0) sBaseSh = atomicAdd(&g_progress[beta], 0u);

    for (int i = tid; i < 96 * 96; i += NTHR) sm[SM_WIH + (i / 96) * 100 + (i % 96)] = Wih[i];
    for (int i = tid; i < 96 * 32; i += NTHR) sm[SM_WHH + (i / 32) * 36  + (i % 32)] = Whh[i];

    const float br0 = bih[c]      + bhh[c];
    const float bz0 = bih[32 + c] + bhh[32 + c];
    const float bni = bih[64 + c];
    const float bnh = bhh[64 + c];

    // zero halo slots of both buffers (edge tiles never overwrite them)
    if (tid < 32) { sm[SM_BUFA + tid] = 0.0f; sm[SM_BUFB + tid] = 0.0f; }
    else if (tid < 64) {
        sm[SM_BUFA + 33 * 32 + (tid - 32)] = 0.0f;
        sm[SM_BUFB + 33 * 32 + (tid - 32)] = 0.0f;
    }
    __syncthreads();
    const unsigned sBase = sBaseSh;

    // Publish column 0 = input column 0 (identity passthrough) into bufA
    for (int i = tid; i < 1024; i += NTHR) {
        int r = i >> 5, cc = i & 31;
        size_t gi = ((size_t)b * 512 + (h0 + r)) * 32 + cc;   // w = 0
        float v = g_Xt[gi];
        sm[SM_BUFA + (1 + r) * 32 + cc] = v;
        g_Yt[gi] = v;
    }
    __threadfence();
    __syncthreads();
    if (tid == 0) atomicExch(&g_progress[beta], sBase + 1);

    // Prefetch input column w=1 into registers (off the critical path)
    float4 xnext = *(const float4*)&g_Xt[((size_t)(1 * 8 + b) * 512 + h0) * 32 + tid * 4];

    // w=1 reads bufA -> writes bufB; then pairs (B->A, A->B)
    gru_step<SM_BUFA, SM_BUFB>(sm, 1, xnext, tid, b, tile, h0, c, rq, beta, sBase,
                               br0, bz0, bni, bnh);
    for (int w = 2; w < W_DIM; w += 2) {
        gru_step<SM_BUFB, SM_BUFA>(sm, w,     xnext, tid, b, tile, h0, c, rq, beta, sBase,
                                   br0, bz0, bni, bnh);
        gru_step<SM_BUFA, SM_BUFB>(sm, w + 1, xnext, tid, b, tile, h0, c, rq, beta, sBase,
                                   br0, bz0, bni, bnh);
    }
}

// ---------------------------------------------------------------------------
extern "C" void kernel_launch(void* const* d_in, const int* in_sizes, int n_in,
                              void* d_out, int out_size) {
    const float* states = (const float*)d_in[0];
    const float* wih    = (const float*)d_in[1];
    const float* bih    = (const float*)d_in[2];
    const float* whh    = (const float*)d_in[3];
    const float* bhh    = (const float*)d_in[4];
    float* out = (float*)d_out;

    cudaFuncSetAttribute(scan_kernel, cudaFuncAttributeMaxDynamicSharedMemorySize,
                         SM_FLOATS * (int)sizeof(float));

    dim3 tgrid(W_DIM / 32, H_DIM, B_DIM);
    transpose_in_kernel<<<tgrid, 256>>>(states);
    scan_kernel<<<NBLK, NTHR, SM_FLOATS * sizeof(float)>>>(wih, bih, whh, bhh);
    transpose_out_kernel<<<tgrid, 256>>>(out);
}